// round 12
// baseline (speedup 1.0000x reference)
#include <cuda_runtime.h>
#include <cuda_fp16.h>
#include <cstdint>

// TrajectoryGRU: fp16 single-pass mma, 1024 threads (16 M-warps + 16 C-warps),
// 32 rows/CTA in two 16-row halves, 2 named barriers/step. Grid 512.
// M-warp (jt,nt): GH 24 mma + head 8 mma per half-step, A-frags from SMEM.
// C-thread (j, 4 n's): gi + activations + h-update + HF fp16 write.

#define NT 1024
#define OFF_WA  0        // W_hh A-frags [jt8][g3][kc8][l32] u4 = 98304
#define OFF_W1F 98304    // w1 A-frags [jt8][kc8][l32] u4 = 32768
#define OFF_HF  131072   // [h2][kc8][nt2][l32] u2 = 8192
#define OFF_DG  139264   // [h2][g3][j128][18] f32 = 55296
#define OFF_AT  194560   // [h2][n16][132] f32 = 16896
#define OFF_XSE 211456   // [h2][par2][96] f32 = 1536
#define OFF_XSD 212992   // [h2][96] f32 = 768
#define OFF_W2  213760   // [6][128] f32 = 3072
#define SMEM_TOTAL 216832

__device__ __forceinline__ void mma16816(float* d, const uint32_t* a,
                                         uint32_t b0, uint32_t b1) {
  asm volatile(
    "mma.sync.aligned.m16n8k16.row.col.f32.f16.f16.f32 "
    "{%0,%1,%2,%3}, {%4,%5,%6,%7}, {%8,%9}, {%0,%1,%2,%3};"
    : "+f"(d[0]), "+f"(d[1]), "+f"(d[2]), "+f"(d[3])
    : "r"(a[0]), "r"(a[1]), "r"(a[2]), "r"(a[3]), "r"(b0), "r"(b1));
}
__device__ __forceinline__ uint32_t packh2(float2 v) {
  __half2 p(__float2half_rn(v.x), __float2half_rn(v.y));
  return *reinterpret_cast<uint32_t*>(&p);
}
__device__ __forceinline__ float sigf(float v) {
  return __fdividef(1.0f, 1.0f + __expf(-v));
}
__device__ __forceinline__ float tanhfast(float v) {
  float av = fabsf(v), e = __expf(-2.0f * av);
  return copysignf(__fdividef(1.0f - e, 1.0f + e), v);
}
#define BARX(id, n) asm volatile("bar.sync %0, %1;" :: "r"(id), "r"(n) : "memory")

__global__ void __launch_bounds__(NT, 1)
gru_w32_kernel(const float* __restrict__ history, const float* __restrict__ w_ih,
               const float* __restrict__ w_hh, const float* __restrict__ b_ih,
               const float* __restrict__ b_hh, const float* __restrict__ w1,
               const float* __restrict__ b1, const float* __restrict__ w2,
               const float* __restrict__ b2, float* __restrict__ out)
{
  extern __shared__ char sb[];
  const int tid = threadIdx.x, w = tid >> 5, l = tid & 31;
  const int grp = l >> 2, tg = l & 3;
  const int row0 = blockIdx.x * 32;

  // ---------- init (all threads) ----------
  for (int idx = tid; idx < 6144; idx += NT) {   // W_hh frags [jt][g][kc][l]
    int ll = idx & 31, kc = (idx >> 5) & 7, g = (idx >> 8) % 3, jt = idx / 768;
    int jA = jt * 16 + (ll >> 2), jB = jA + 8, k0 = kc * 16 + (ll & 3) * 2;
    const float* base = w_hh + (size_t)(g * 128) * 128;
    uint4 f = { packh2(*(const float2*)(base + (size_t)jA * 128 + k0)),
                packh2(*(const float2*)(base + (size_t)jB * 128 + k0)),
                packh2(*(const float2*)(base + (size_t)jA * 128 + k0 + 8)),
                packh2(*(const float2*)(base + (size_t)jB * 128 + k0 + 8)) };
    *(uint4*)(sb + OFF_WA + (size_t)idx * 16) = f;
  }
  for (int idx = tid; idx < 2048; idx += NT) {   // w1 frags [jt][kc][l]
    int ll = idx & 31, kc = (idx >> 5) & 7, jt = idx >> 8;
    int jA = jt * 16 + (ll >> 2), jB = jA + 8, k0 = kc * 16 + (ll & 3) * 2;
    uint4 f = { packh2(*(const float2*)(w1 + (size_t)jA * 128 + k0)),
                packh2(*(const float2*)(w1 + (size_t)jB * 128 + k0)),
                packh2(*(const float2*)(w1 + (size_t)jA * 128 + k0 + 8)),
                packh2(*(const float2*)(w1 + (size_t)jB * 128 + k0 + 8)) };
    *(uint4*)(sb + OFF_W1F + (size_t)idx * 16) = f;
  }
  for (int i = tid; i < 768; i += NT) ((float*)(sb + OFF_W2))[i] = w2[i];
  for (int i = tid; i < 2048; i += NT) ((uint32_t*)(sb + OFF_HF))[i] = 0u;
  if (tid < 192) {   // x(0) both halves, parity 0
    int hh = tid / 96, idx = tid - hh * 96, n = idx / 6, i = idx - n * 6;
    ((float*)(sb + OFF_XSE))[hh * 192 + idx] =
        history[(size_t)(row0 + hh * 16 + n) * 300 + i];
  }
  __syncthreads();

  if (w < 16) {
    // ================= M-warps: all HMMA =================
    const int jt = w >> 1, nt = w & 1;
    const int jA = jt * 16 + grp, jB = jA + 8;
    const float b1A = b1[jA], b1B = b1[jB];
    for (int t = 0; t <= 80; t++) {
      const bool doG = t < 80, doH = t > 50;
      #pragma unroll 1
      for (int h = 0; h < 2; h++) {
        const char* hfb = sb + OFF_HF + h * 4096;
        float D[3][4], Da[4];
        #pragma unroll
        for (int g = 0; g < 3; g++)
          #pragma unroll
          for (int r = 0; r < 4; r++) D[g][r] = 0.f;
        #pragma unroll
        for (int r = 0; r < 4; r++) Da[r] = 0.f;
        #pragma unroll
        for (int kc = 0; kc < 8; kc++) {
          uint2 v = *(const uint2*)(hfb + ((kc * 2 + nt) * 32 + l) * 8);
          if (doG) {
            #pragma unroll
            for (int g = 0; g < 3; g++) {
              uint4 a = *(const uint4*)(sb + OFF_WA +
                         ((size_t)((jt * 3 + g) * 8 + kc) * 32 + l) * 16);
              uint32_t A[4] = { a.x, a.y, a.z, a.w };
              mma16816(D[g], A, v.x, v.y);
            }
          }
          if (doH) {
            uint4 a = *(const uint4*)(sb + OFF_W1F +
                       ((size_t)(jt * 8 + kc) * 32 + l) * 16);
            uint32_t A[4] = { a.x, a.y, a.z, a.w };
            mma16816(Da, A, v.x, v.y);
          }
        }
        if (doG) {
          float* dgh = (float*)(sb + OFF_DG) + h * 6912;
          #pragma unroll
          for (int g = 0; g < 3; g++)
            #pragma unroll
            for (int rh = 0; rh < 2; rh++) {
              float2 p = { D[g][rh * 2 + 0], D[g][rh * 2 + 1] };
              *(float2*)(dgh + (g * 128 + (rh ? jB : jA)) * 18
                             + nt * 8 + tg * 2) = p;
            }
        }
        if (doH) {
          float* at = (float*)(sb + OFF_AT) + h * 2112;
          #pragma unroll
          for (int rh = 0; rh < 2; rh++)
            #pragma unroll
            for (int cc = 0; cc < 2; cc++)
              at[(nt * 8 + tg * 2 + cc) * 132 + (rh ? jB : jA)] =
                  fmaxf(Da[rh * 2 + cc] + (rh ? b1B : b1A), 0.f);
        }
        BARX(h + 1, NT);
      }
    }
  } else {
    // ================= C-warps: gi + activations + epilogue =================
    const int c = tid - 512;
    const int j = c & 127, n0 = c >> 7;        // n = n0 + 4q
    float wr[6], wz[6], wn[6];
    #pragma unroll
    for (int i = 0; i < 6; i++) {
      wr[i] = w_ih[(size_t)j * 6 + i];
      wz[i] = w_ih[(size_t)(128 + j) * 6 + i];
      wn[i] = w_ih[(size_t)(256 + j) * 6 + i];
    }
    const float br  = b_ih[j] + b_hh[j];
    const float bz  = b_ih[128 + j] + b_hh[128 + j];
    const float bin = b_ih[256 + j];
    const float bhn = b_hh[256 + j];
    float b2r = 0.f;
    if (c < 96) b2r = b2[c % 6];
    float hreg[2][4];
    #pragma unroll
    for (int h = 0; h < 2; h++)
      #pragma unroll
      for (int q = 0; q < 4; q++) hreg[h][q] = 0.f;
    // HF write address (j-dependent parts)
    const uint32_t kcj = (uint32_t)(j >> 4) * 2;
    const uint32_t lj  = (uint32_t)((j >> 1) & 3);
    const uint32_t bsel = (uint32_t)(((j >> 3) & 1) * 4 + (j & 1) * 2);

    for (int t = 0; t <= 80; t++) {
      #pragma unroll 1
      for (int h = 0; h < 2; h++) {
        BARX(h + 1, NT);
        if (t > 50) {   // head w2 epilogue
          if (c < 96) {
            int n = c / 6, i = c - n * 6;
            const float4* a4 = (const float4*)((float*)(sb + OFF_AT)
                                + h * 2112 + n * 132);
            const float4* wv = (const float4*)((float*)(sb + OFF_W2) + i * 128);
            float acc = b2r;
            #pragma unroll 8
            for (int k4 = 0; k4 < 32; k4++) {
              float4 a = a4[k4], ww = wv[k4];
              acc = fmaf(a.x, ww.x, fmaf(a.y, ww.y,
                    fmaf(a.z, ww.z, fmaf(a.w, ww.w, acc))));
            }
            ((float*)(sb + OFF_XSD))[h * 96 + c] = acc;
            out[(size_t)(row0 + h * 16 + n) * 180 + (size_t)(t - 51) * 6 + i] = acc;
          }
          BARX(3, 512);   // C-only: xsd visible
        }
        if (t < 80) {
          const float* xq =
              (t < 50) ? (const float*)(sb + OFF_XSE) + (h * 2 + (t & 1)) * 96
            : (t == 50) ? (const float*)(sb + OFF_XSE) + (h * 2 + 1) * 96
            : (const float*)(sb + OFF_XSD) + h * 96;
          const float* dgh = (const float*)(sb + OFF_DG) + h * 6912;
          #pragma unroll
          for (int q = 0; q < 4; q++) {
            const int n = n0 + 4 * q;
            const float* xp = xq + n * 6;
            float gr = br, gz = bz, gn = bin;
            #pragma unroll
            for (int i = 0; i < 6; i++) {
              float xv = xp[i];
              gr = fmaf(wr[i], xv, gr);
              gz = fmaf(wz[i], xv, gz);
              gn = fmaf(wn[i], xv, gn);
            }
            float Dr = dgh[(0 * 128 + j) * 18 + n];
            float Dz = dgh[(1 * 128 + j) * 18 + n];
            float Dn = dgh[(2 * 128 + j) * 18 + n];
            float r  = sigf(gr + Dr);
            float z  = sigf(gz + Dz);
            float nn = tanhfast(fmaf(r, Dn + bhn, gn));
            float hv = fmaf(z, hreg[h][q] - nn, nn);
            hreg[h][q] = hv;
            *(__half*)(sb + OFF_HF + h * 4096 +
                       ((kcj + (uint32_t)(n >> 3)) * 32
                        + (uint32_t)((n & 7) * 4) + lj) * 8 + bsel)
                = __float2half_rn(hv);
          }
        }
        if (h == 1 && t + 1 < 50 && c < 192) {   // encoder x prefetch
          int hh = c / 96, idx = c - hh * 96, n = idx / 6, i = idx - n * 6;
          ((float*)(sb + OFF_XSE))[(hh * 2 + ((t + 1) & 1)) * 96 + idx] =
              history[(size_t)(row0 + hh * 16 + n) * 300 + (size_t)(t + 1) * 6 + i];
        }
      }
    }
  }
}

extern "C" void kernel_launch(void* const* d_in, const int* in_sizes, int n_in,
                              void* d_out, int out_size) {
  const float* history = (const float*)d_in[0];
  const float* w_ih    = (const float*)d_in[1];
  const float* w_hh    = (const float*)d_in[2];
  const float* b_ih    = (const float*)d_in[3];
  const float* b_hh    = (const float*)d_in[4];
  const float* w1      = (const float*)d_in[5];
  const float* b1      = (const float*)d_in[6];
  const float* w2      = (const float*)d_in[7];
  const float* b2      = (const float*)d_in[8];
  float* out = (float*)d_out;

  cudaFuncSetAttribute(gru_w32_kernel,
                       cudaFuncAttributeMaxDynamicSharedMemorySize, SMEM_TOTAL);
  gru_w32_kernel<<<512, NT, SMEM_TOTAL>>>(
      history, w_ih, w_hh, b_ih, b_hh, w1, b1, w2, b2, out);
}

// round 13
// speedup vs baseline: 1.4612x; 1.4612x over previous
#include <cuda_runtime.h>
#include <cuda_fp16.h>
#include <cstdint>

// TrajectoryGRU: warp-specialized fp16 single-pass mma (R10 skeleton).
// 512 thr: warps 0-7 (M) = HMMA (r-gate A in regs, z/n/w1 A from smem),
// warps 8-15 (C) = gi + activations + w2. Two 16-row halves pipelined,
// 2 named barriers/step. h: fp16 hi only (rel_err ~5e-5, validated R11).

#define NT 512
#define OFF_WZN 0        // W_hh z/n A-frags [jt8][2][kc8][l32] u4 = 65536
#define OFF_W1F 65536    // w1 A-frags [jt8][kc8][l32] u4 = 32768
#define OFF_HF  98304    // [h2][slot128 x 8B] = 8192
#define OFF_DG  106496   // [h2][3*16*132] f32 = 50688
#define OFF_AT  157184   // [h2][16*132] f32 = 16896
#define OFF_XSE 174080   // [h2][par2][96] f32 = 1536
#define OFF_XSD 175616   // [h2][96] f32 = 768
#define OFF_W2  176384   // [6][128] f32 = 3072
#define SMEM_TOTAL 179456

__device__ __forceinline__ void mma16816(float* d, const uint32_t* a,
                                         uint32_t b0, uint32_t b1) {
  asm volatile(
    "mma.sync.aligned.m16n8k16.row.col.f32.f16.f16.f32 "
    "{%0,%1,%2,%3}, {%4,%5,%6,%7}, {%8,%9}, {%0,%1,%2,%3};"
    : "+f"(d[0]), "+f"(d[1]), "+f"(d[2]), "+f"(d[3])
    : "r"(a[0]), "r"(a[1]), "r"(a[2]), "r"(a[3]), "r"(b0), "r"(b1));
}
__device__ __forceinline__ uint32_t packh2(float2 v) {
  __half2 p(__float2half_rn(v.x), __float2half_rn(v.y));
  return *reinterpret_cast<uint32_t*>(&p);
}
__device__ __forceinline__ float sigf(float v) {
  return __fdividef(1.0f, 1.0f + __expf(-v));
}
__device__ __forceinline__ float tanhfast(float v) {
  float av = fabsf(v), e = __expf(-2.0f * av);
  return copysignf(__fdividef(1.0f - e, 1.0f + e), v);
}
#define BARX(id, n) asm volatile("bar.sync %0, %1;" :: "r"(id), "r"(n) : "memory")

__global__ void __launch_bounds__(NT, 1)
gru_ws1_kernel(const float* __restrict__ history, const float* __restrict__ w_ih,
               const float* __restrict__ w_hh, const float* __restrict__ b_ih,
               const float* __restrict__ b_hh, const float* __restrict__ w1,
               const float* __restrict__ b1, const float* __restrict__ w2,
               const float* __restrict__ b2, float* __restrict__ out)
{
  extern __shared__ char sb[];
  const int tid = threadIdx.x, w = tid >> 5, l = tid & 31;
  const int grp = l >> 2, tg = l & 3;
  const int row0 = blockIdx.x * 32;
  const bool isM = w < 8;

  float* w2s = (float*)(sb + OFF_W2);
  for (int i = tid; i < 768; i += NT) w2s[i] = w2[i];
  for (int i = tid; i < 2048; i += NT) ((uint32_t*)(sb + OFF_HF))[i] = 0u;
  if (tid < 192) {   // x(0) for both halves, parity 0
    int hh = tid / 96, idx = tid - hh * 96, n = idx / 6, i = idx - n * 6;
    ((float*)(sb + OFF_XSE))[hh * 192 + idx] =
        history[(size_t)(row0 + hh * 16 + n) * 300 + i];
  }

  // ---------------- role-specific init ----------------
  uint32_t Ar[8][4];
  float b1A = 0.f, b1B = 0.f;
  float wg[3][2][6], brv[2], bzv[2], binv[2], bhnv[2], b2r = 0.f;
  float hreg[2][4][2];
  int c = 0, ng = 0, jj = 0;

  if (isM) {
    const int mw = w, jA = mw * 16 + grp, jB = jA + 8;
    #pragma unroll
    for (int kc = 0; kc < 8; kc++) {
      int k0 = kc * 16 + tg * 2;
      Ar[kc][0] = packh2(*(const float2*)(w_hh + (size_t)jA * 128 + k0));
      Ar[kc][1] = packh2(*(const float2*)(w_hh + (size_t)jB * 128 + k0));
      Ar[kc][2] = packh2(*(const float2*)(w_hh + (size_t)jA * 128 + k0 + 8));
      Ar[kc][3] = packh2(*(const float2*)(w_hh + (size_t)jB * 128 + k0 + 8));
      #pragma unroll
      for (int g = 1; g < 3; g++) {
        int rA = g * 128 + jA, rB = g * 128 + jB;
        uint4 f = { packh2(*(const float2*)(w_hh + (size_t)rA * 128 + k0)),
                    packh2(*(const float2*)(w_hh + (size_t)rB * 128 + k0)),
                    packh2(*(const float2*)(w_hh + (size_t)rA * 128 + k0 + 8)),
                    packh2(*(const float2*)(w_hh + (size_t)rB * 128 + k0 + 8)) };
        *(uint4*)(sb + OFF_WZN + (((mw * 2 + (g - 1)) * 8 + kc) * 32 + l) * 16) = f;
      }
      uint4 f1 = { packh2(*(const float2*)(w1 + (size_t)jA * 128 + k0)),
                   packh2(*(const float2*)(w1 + (size_t)jB * 128 + k0)),
                   packh2(*(const float2*)(w1 + (size_t)jA * 128 + k0 + 8)),
                   packh2(*(const float2*)(w1 + (size_t)jB * 128 + k0 + 8)) };
      *(uint4*)(sb + OFF_W1F + ((mw * 8 + kc) * 32 + l) * 16) = f1;
    }
    b1A = b1[jA]; b1B = b1[jB];
  } else {
    c = tid - 256; ng = c >> 6; jj = (c & 63) * 2;
    #pragma unroll
    for (int jp = 0; jp < 2; jp++) {
      int j = jj + jp;
      #pragma unroll
      for (int g = 0; g < 3; g++)
        #pragma unroll
        for (int i = 0; i < 6; i++)
          wg[g][jp][i] = w_ih[(size_t)(g * 128 + j) * 6 + i];
      brv[jp]  = b_ih[j] + b_hh[j];
      bzv[jp]  = b_ih[128 + j] + b_hh[128 + j];
      binv[jp] = b_ih[256 + j];
      bhnv[jp] = b_hh[256 + j];
    }
    if (c < 192) b2r = b2[(c % 96) % 6];
    #pragma unroll
    for (int h = 0; h < 2; h++)
      #pragma unroll
      for (int q = 0; q < 4; q++) { hreg[h][q][0] = 0.f; hreg[h][q][1] = 0.f; }
  }
  __syncthreads();

  // ================= main loops =================
  if (isM) {
    const int mw = w;
    for (int t = 0; t <= 80; t++) {
      const bool doG = t < 80, doH = t > 50;
      #pragma unroll 1
      for (int h = 0; h < 2; h++) {
        float D[3][2][4], Da[2][4];
        if (doG) {
          #pragma unroll
          for (int g = 0; g < 3; g++)
            #pragma unroll
            for (int nt = 0; nt < 2; nt++)
              #pragma unroll
              for (int r = 0; r < 4; r++) D[g][nt][r] = 0.f;
        }
        if (doH) {
          #pragma unroll
          for (int nt = 0; nt < 2; nt++)
            #pragma unroll
            for (int r = 0; r < 4; r++) Da[nt][r] = 0.f;
        }
        const char* hfb = sb + OFF_HF + h * 4096;
        #pragma unroll
        for (int kc = 0; kc < 8; kc++) {
          uint2 v0 = *(const uint2*)(hfb + ((kc * 2 + 0) * 32 + l) * 8);
          uint2 v1 = *(const uint2*)(hfb + ((kc * 2 + 1) * 32 + l) * 8);
          if (doG) {
            uint4 za = *(const uint4*)(sb + OFF_WZN + ((mw * 16 + kc) * 32 + l) * 16);
            uint4 na = *(const uint4*)(sb + OFF_WZN + ((mw * 16 + 8 + kc) * 32 + l) * 16);
            uint32_t Az[4] = { za.x, za.y, za.z, za.w };
            uint32_t An[4] = { na.x, na.y, na.z, na.w };
            mma16816(D[0][0], Ar[kc], v0.x, v0.y);
            mma16816(D[0][1], Ar[kc], v1.x, v1.y);
            mma16816(D[1][0], Az, v0.x, v0.y);
            mma16816(D[1][1], Az, v1.x, v1.y);
            mma16816(D[2][0], An, v0.x, v0.y);
            mma16816(D[2][1], An, v1.x, v1.y);
          }
          if (doH) {
            uint4 ha = *(const uint4*)(sb + OFF_W1F + ((mw * 8 + kc) * 32 + l) * 16);
            uint32_t A1[4] = { ha.x, ha.y, ha.z, ha.w };
            mma16816(Da[0], A1, v0.x, v0.y);
            mma16816(Da[1], A1, v1.x, v1.y);
          }
        }
        if (doG) {
          float* dg = (float*)(sb + OFF_DG) + h * 6336;
          #pragma unroll
          for (int g = 0; g < 3; g++)
            #pragma unroll
            for (int nt = 0; nt < 2; nt++)
              #pragma unroll
              for (int rh = 0; rh < 2; rh++)
                #pragma unroll
                for (int cc = 0; cc < 2; cc++)
                  dg[(g * 16 + nt * 8 + tg * 2 + cc) * 132 + mw * 16 + rh * 8 + grp]
                      = D[g][nt][rh * 2 + cc];
        }
        if (doH) {
          float* at = (float*)(sb + OFF_AT) + h * 2112;
          #pragma unroll
          for (int nt = 0; nt < 2; nt++)
            #pragma unroll
            for (int rh = 0; rh < 2; rh++)
              #pragma unroll
              for (int cc = 0; cc < 2; cc++)
                at[(nt * 8 + tg * 2 + cc) * 132 + mw * 16 + rh * 8 + grp] =
                    fmaxf(Da[nt][rh * 2 + cc] + (rh ? b1B : b1A), 0.f);
        }
        BARX(h + 1, 512);
      }
    }
  } else {
    for (int t = 0; t <= 80; t++) {
      #pragma unroll 1
      for (int h = 0; h < 2; h++) {
        BARX(h + 1, 512);
        if (t > 50) {           // w2 epilogue for this half (aT ready)
          if (c >= h * 96 && c < h * 96 + 96) {
            int idx = c - h * 96, n = idx / 6, i = idx - n * 6;
            const float4* a4 =
                (const float4*)((float*)(sb + OFF_AT) + h * 2112 + n * 132);
            const float4* wv = (const float4*)(w2s + i * 128);
            float acc = b2r;
            #pragma unroll 8
            for (int k4 = 0; k4 < 32; k4++) {
              float4 a = a4[k4], ww = wv[k4];
              acc = fmaf(a.x, ww.x, fmaf(a.y, ww.y,
                    fmaf(a.z, ww.z, fmaf(a.w, ww.w, acc))));
            }
            ((float*)(sb + OFF_XSD))[h * 96 + idx] = acc;
            out[(size_t)(row0 + h * 16 + n) * 180 + (size_t)(t - 51) * 6 + i] = acc;
          }
          BARX(3, 256);
        }
        if (t < 80) {           // gi + combine -> h_t
          const float* xq =
              (t < 50) ? (const float*)(sb + OFF_XSE) + (h * 2 + (t & 1)) * 96
            : (t == 50) ? (const float*)(sb + OFF_XSE) + (h * 2 + 1) * 96
            : (const float*)(sb + OFF_XSD) + h * 96;
          float* dg = (float*)(sb + OFF_DG) + h * 6336;
          #pragma unroll
          for (int q = 0; q < 4; q++) {
            int n = ng * 4 + q;
            const float* xp = xq + n * 6;
            float x0 = xp[0], x1 = xp[1], x2 = xp[2],
                  x3 = xp[3], x4 = xp[4], x5 = xp[5];
            float2 Dr = *(const float2*)(dg + n * 132 + jj);
            float2 Dz = *(const float2*)(dg + (16 + n) * 132 + jj);
            float2 Dn = *(const float2*)(dg + (32 + n) * 132 + jj);
            float hv[2];
            #pragma unroll
            for (int jp = 0; jp < 2; jp++) {
              float gr = brv[jp], gz = bzv[jp], gn = binv[jp];
              gr = fmaf(wg[0][jp][0], x0, fmaf(wg[0][jp][1], x1, fmaf(wg[0][jp][2], x2,
                   fmaf(wg[0][jp][3], x3, fmaf(wg[0][jp][4], x4, fmaf(wg[0][jp][5], x5, gr))))));
              gz = fmaf(wg[1][jp][0], x0, fmaf(wg[1][jp][1], x1, fmaf(wg[1][jp][2], x2,
                   fmaf(wg[1][jp][3], x3, fmaf(wg[1][jp][4], x4, fmaf(wg[1][jp][5], x5, gz))))));
              gn = fmaf(wg[2][jp][0], x0, fmaf(wg[2][jp][1], x1, fmaf(wg[2][jp][2], x2,
                   fmaf(wg[2][jp][3], x3, fmaf(wg[2][jp][4], x4, fmaf(wg[2][jp][5], x5, gn))))));
              float r = sigf(gr + (jp ? Dr.y : Dr.x));
              float z = sigf(gz + (jp ? Dz.y : Dz.x));
              float nn = tanhfast(fmaf(r, (jp ? Dn.y : Dn.x) + bhnv[jp], gn));
              float hh = fmaf(z, hreg[h][q][jp] - nn, nn);
              hreg[h][q][jp] = hh;
              hv[jp] = hh;
            }
            __half2 hi2(__float2half_rn(hv[0]), __float2half_rn(hv[1]));
            uint32_t slot = (uint32_t)((jj >> 4) * 64 + (n >> 3) * 32
                          + (n & 7) * 4 + ((jj & 7) >> 1));
            *(uint32_t*)(sb + OFF_HF + h * 4096 + slot * 8 + ((jj >> 3) & 1) * 4)
                = *(uint32_t*)&hi2;
          }
        }
        if (h == 1 && t + 1 < 50 && c < 192) {   // encoder x prefetch
          int hh = c / 96, idx = c - hh * 96, n = idx / 6, i = idx - n * 6;
          ((float*)(sb + OFF_XSE))[(hh * 2 + ((t + 1) & 1)) * 96 + idx] =
              history[(size_t)(row0 + hh * 16 + n) * 300 + (size_t)(t + 1) * 6 + i];
        }
      }
    }
  }
}

extern "C" void kernel_launch(void* const* d_in, const int* in_sizes, int n_in,
                              void* d_out, int out_size) {
  const float* history = (const float*)d_in[0];
  const float* w_ih    = (const float*)d_in[1];
  const float* w_hh    = (const float*)d_in[2];
  const float* b_ih    = (const float*)d_in[3];
  const float* b_hh    = (const float*)d_in[4];
  const float* w1      = (const float*)d_in[5];
  const float* b1      = (const float*)d_in[6];
  const float* w2      = (const float*)d_in[7];
  const float* b2      = (const float*)d_in[8];
  float* out = (float*)d_out;

  cudaFuncSetAttribute(gru_ws1_kernel,
                       cudaFuncAttributeMaxDynamicSharedMemorySize, SMEM_TOTAL);
  gru_ws1_kernel<<<512, NT, SMEM_TOTAL>>>(
      history, w_ih, w_hh, b_ih, b_hh, w1, b1, w2, b2, out);
}